// round 7
// baseline (speedup 1.0000x reference)
#include <cuda_runtime.h>
#include <cuda_bf16.h>
#include <stdint.h>

// Flash attention, B=32, LQ=LK=2048, D=128, fp32 in/out. HMMA path.
// Mask: 4-byte elems (bool promoted); nonzero = masked. score=(q.k)*sqrt(128).
// Precision: bf16 hi/lo split, 3-term MMA for QK^T and PV.
// R6: 2 CTAs/SM x 4 warps (BR=64) -> each SMSP gets 2 warps from INDEPENDENT
// CTAs, decorrelating stalls (prior rounds: 2 same-CTA warps pinned tensor=41%).

namespace {

constexpr int B_   = 32;
constexpr int LQ_  = 2048;
constexpr int LK_  = 2048;
constexpr int DH   = 128;
constexpr int BR   = 64;    // query rows per CTA
constexpr int BC   = 64;    // keys per iteration
constexpr int NTH  = 128;   // 4 warps
constexpr int NIT  = LK_ / BC;
constexpr int RSB  = 272;   // 128 bf16 + 8B pad

constexpr int PLANE = BC * RSB;       // 17408 B
constexpr int KSTG  = 2 * PLANE;      // hi+lo: 34816 B
constexpr int SM_K  = 0;              // 2 stages: 69632
constexpr int SM_V  = 2 * KSTG;       // 1 stage: 34816 -> ends 104448
constexpr int SM_MSK = SM_V + KSTG;   // 104448
constexpr int MROW  = 68;
constexpr int SM_TOT = SM_MSK + BR * MROW;   // 108800 B (2 CTAs fit in 227KB)

// Q prologue staging overlays the K region (34816 B <= 69632)
constexpr int SM_QHI = 0;
constexpr int SM_QLO = BR * RSB;

__device__ __nv_bfloat16 g_khi[(size_t)B_ * LK_ * DH];
__device__ __nv_bfloat16 g_klo[(size_t)B_ * LK_ * DH];
__device__ __nv_bfloat16 g_vhi[(size_t)B_ * LK_ * DH];
__device__ __nv_bfloat16 g_vlo[(size_t)B_ * LK_ * DH];

__device__ __forceinline__ uint32_t smem_u32(const void* p) {
    return (uint32_t)__cvta_generic_to_shared(p);
}
__device__ __forceinline__ void cp16(uint32_t dst, const void* src) {
    asm volatile("cp.async.cg.shared.global [%0], [%1], 16;" :: "r"(dst), "l"(src));
}
#define CP_COMMIT() asm volatile("cp.async.commit_group;")
#define CP_WAIT0()  asm volatile("cp.async.wait_group 0;")

__device__ __forceinline__ void ldsm4(uint32_t r[4], uint32_t a) {
    asm volatile("ldmatrix.sync.aligned.m8n8.x4.shared.b16 {%0,%1,%2,%3}, [%4];"
                 : "=r"(r[0]), "=r"(r[1]), "=r"(r[2]), "=r"(r[3]) : "r"(a));
}
__device__ __forceinline__ void ldsm4t(uint32_t r[4], uint32_t a) {
    asm volatile("ldmatrix.sync.aligned.m8n8.x4.trans.shared.b16 {%0,%1,%2,%3}, [%4];"
                 : "=r"(r[0]), "=r"(r[1]), "=r"(r[2]), "=r"(r[3]) : "r"(a));
}
__device__ __forceinline__ void mma_bf16(float d[4], const uint32_t a[4], uint32_t b0, uint32_t b1) {
    asm volatile("mma.sync.aligned.m16n8k16.row.col.f32.bf16.bf16.f32 "
                 "{%0,%1,%2,%3}, {%4,%5,%6,%7}, {%8,%9}, {%0,%1,%2,%3};"
                 : "+f"(d[0]), "+f"(d[1]), "+f"(d[2]), "+f"(d[3])
                 : "r"(a[0]), "r"(a[1]), "r"(a[2]), "r"(a[3]), "r"(b0), "r"(b1));
}
__device__ __forceinline__ float ex2f(float x) {
    float y; asm("ex2.approx.f32 %0, %1;" : "=f"(y) : "f"(x)); return y;
}
__device__ __forceinline__ uint32_t bits2(__nv_bfloat162 h) {
    uint32_t u; __builtin_memcpy(&u, &h, 4); return u;
}
__device__ __forceinline__ void split_store(float4 f, char* ph, char* pl) {
    __nv_bfloat16 h0 = __float2bfloat16_rn(f.x);
    __nv_bfloat16 h1 = __float2bfloat16_rn(f.y);
    __nv_bfloat16 h2 = __float2bfloat16_rn(f.z);
    __nv_bfloat16 h3 = __float2bfloat16_rn(f.w);
    *(__nv_bfloat162*)(ph)     = __halves2bfloat162(h0, h1);
    *(__nv_bfloat162*)(ph + 4) = __halves2bfloat162(h2, h3);
    __nv_bfloat16 l0 = __float2bfloat16_rn(f.x - __bfloat162float(h0));
    __nv_bfloat16 l1 = __float2bfloat16_rn(f.y - __bfloat162float(h1));
    __nv_bfloat16 l2 = __float2bfloat16_rn(f.z - __bfloat162float(h2));
    __nv_bfloat16 l3 = __float2bfloat16_rn(f.w - __bfloat162float(h3));
    *(__nv_bfloat162*)(pl)     = __halves2bfloat162(l0, l1);
    *(__nv_bfloat162*)(pl + 4) = __halves2bfloat162(l2, l3);
}
__device__ __forceinline__ void split_pair(float x, float y, uint32_t& hi, uint32_t& lo) {
    __nv_bfloat16 hx = __float2bfloat16_rn(x);
    __nv_bfloat16 hy = __float2bfloat16_rn(y);
    hi = bits2(__halves2bfloat162(hx, hy));
    __nv_bfloat16 lx = __float2bfloat16_rn(x - __bfloat162float(hx));
    __nv_bfloat16 ly = __float2bfloat16_rn(y - __bfloat162float(hy));
    lo = bits2(__halves2bfloat162(lx, ly));
}

__global__ void __launch_bounds__(256, 4)
conv_kernel(const float* __restrict__ kg, const float* __restrict__ vg)
{
    size_t i4 = ((size_t)blockIdx.x * 256 + threadIdx.x) * 4;
    float4 fk = *(const float4*)(kg + i4);
    split_store(fk, (char*)(g_khi + i4), (char*)(g_klo + i4));
    float4 fv = *(const float4*)(vg + i4);
    split_store(fv, (char*)(g_vhi + i4), (char*)(g_vlo + i4));
}

__global__ void __launch_bounds__(NTH, 2)
fa_bf16x3_kernel(const float* __restrict__ qg, const uint32_t* __restrict__ mg,
                 float* __restrict__ og)
{
    extern __shared__ char smem[];
    const int tid  = threadIdx.x;
    const int lane = tid & 31;
    const int warp = tid >> 5;
    const int b    = blockIdx.y;
    const int q0   = blockIdx.x * BR;

    const float K2  = 16.3222312f;   // sqrt(128) * log2(e)
    const float NEG = -1e30f;
    const uint32_t sm0 = smem_u32(smem);

    // ---- prologue: Q tile (64x128 fp32) -> bf16 hi/lo smem (overlays K) ----
    {
        const float* qp = qg + ((size_t)b * LQ_ + q0) * DH;
        #pragma unroll
        for (int i = 0; i < 16; ++i) {
            int idx = tid + i * NTH;          // 2048 float4
            int row = idx >> 5, c4 = idx & 31;
            float4 f = *(const float4*)(qp + (size_t)row * DH + c4 * 4);
            split_store(f, smem + SM_QHI + row * RSB + c4 * 8,
                           smem + SM_QLO + row * RSB + c4 * 8);
        }
    }
    __syncthreads();

    uint32_t qa_hi[8][4], qa_lo[8][4];
    {
        uint32_t base = sm0 + (uint32_t)((warp * 16 + (lane & 15)) * RSB + (lane >> 4) * 16);
        #pragma unroll
        for (int kb = 0; kb < 8; ++kb) {
            ldsm4(qa_hi[kb], base + SM_QHI + kb * 32);
            ldsm4(qa_lo[kb], base + SM_QLO + kb * 32);
        }
    }
    __syncthreads();

    // ---- fill helpers: 64x128 bf16 plane pair (hi+lo) = 2048 cp16, 16/thread ----
    const size_t kvoff0 = (size_t)b * LK_ * DH;
    auto fill_K = [&](int kt2) {
        size_t off = kvoff0 + (size_t)kt2 * BC * DH;
        uint32_t dst0 = sm0 + (uint32_t)(SM_K + (kt2 & 1) * KSTG);
        #pragma unroll
        for (int i = 0; i < 16; ++i) {
            int idx = tid + i * NTH;          // 0..2047
            int p = idx >> 10, r = (idx >> 4) & 63, c = idx & 15;
            const __nv_bfloat16* src = (p == 0 ? g_khi : g_klo) + off + (size_t)r * DH + c * 8;
            cp16(dst0 + (uint32_t)(p * PLANE + r * RSB + c * 16), src);
        }
    };
    auto fill_V = [&](int kt2) {
        size_t off = kvoff0 + (size_t)kt2 * BC * DH;
        uint32_t dst0 = sm0 + (uint32_t)SM_V;
        #pragma unroll
        for (int i = 0; i < 16; ++i) {
            int idx = tid + i * NTH;
            int p = idx >> 10, r = (idx >> 4) & 63, c = idx & 15;
            const __nv_bfloat16* src = (p == 0 ? g_vhi : g_vlo) + off + (size_t)r * DH + c * 8;
            cp16(dst0 + (uint32_t)(p * PLANE + r * RSB + c * 16), src);
        }
    };

    // ---- mask prefetch (registers) + warp-local smem pack ----
    const int mrow_w = warp * 16 + (lane >> 1);       // 0..63
    const uint32_t* mp_row = mg + (size_t)b * LQ_ * LK_ + (size_t)(q0 + mrow_w) * LK_
                                + (size_t)(lane & 1) * 32;
    uint32_t pk[8];
    auto ldgm = [&](int kt2) {
        const uint32_t* mp = mp_row + (size_t)kt2 * BC;
        #pragma unroll
        for (int j = 0; j < 8; ++j) {
            uint4 m = *(const uint4*)(mp + j * 4);
            pk[j] = (m.x ? 1u : 0u) | ((m.y ? 1u : 0u) << 8) |
                    ((m.z ? 1u : 0u) << 16) | ((m.w ? 1u : 0u) << 24);
        }
    };

    // prologue fills: K(0), V(0)
    fill_K(0);
    fill_V(0);
    CP_COMMIT();
    ldgm(0);

    float acc[16][4];
    #pragma unroll
    for (int j = 0; j < 16; ++j) { acc[j][0]=0.f; acc[j][1]=0.f; acc[j][2]=0.f; acc[j][3]=0.f; }
    float m0r = NEG, m1r = NEG, l0r = 0.f, l1r = 0.f;

    const int r0l = warp * 16 + (lane >> 2);          // 0..63
    const uint32_t kf_lane = (uint32_t)((lane & 7) * RSB + (lane >> 3) * 16);
    const uint32_t vf_lane = (uint32_t)((lane & 15) * RSB + (lane >> 4) * 16);
    char* mskw = smem + SM_MSK + mrow_w * MROW + (lane & 1) * 32;
    const char* mrd0 = smem + SM_MSK + r0l * MROW;
    const char* mrd1 = mrd0 + 8 * MROW;

    #pragma unroll 1
    for (int kt = 0; kt < NIT; ++kt) {
        CP_WAIT0();            // K(kt), V(kt) (and K(kt+1)-fill from prev iter) done
        __syncthreads();

        // fill K(kt+1) into the alternate stage (readers finished last iter)
        if (kt + 1 < NIT) fill_K(kt + 1);
        CP_COMMIT();

        // stage mask(kt) (warp-local rows), prefetch mask(kt+1)
        #pragma unroll
        for (int j = 0; j < 8; ++j) *(uint32_t*)(mskw + j * 4) = pk[j];
        __syncwarp();
        if (kt + 1 < NIT) ldgm(kt + 1);

        const uint32_t kfb = sm0 + (uint32_t)(SM_K + (kt & 1) * KSTG) + kf_lane;
        const uint32_t vfb = sm0 + (uint32_t)SM_V + vf_lane;

        // ---- S = Q K^T (bf16x3) ----
        float s[8][4];
        #pragma unroll
        for (int nb = 0; nb < 8; ++nb) { s[nb][0]=0.f; s[nb][1]=0.f; s[nb][2]=0.f; s[nb][3]=0.f; }
        #pragma unroll
        for (int kp2 = 0; kp2 < 4; ++kp2) {
            const int kb0 = 2 * kp2, kb1 = 2 * kp2 + 1;
            #pragma unroll
            for (int nbp = 0; nbp < 4; ++nbp) {
                const int n0 = 2 * nbp, n1 = 2 * nbp + 1;
                const uint32_t ka0 = kfb + (uint32_t)(n0 * 8 * RSB + kp2 * 64);
                const uint32_t ka1 = kfb + (uint32_t)(n1 * 8 * RSB + kp2 * 64);
                uint32_t bh0[4], bh1[4], bl0[4], bl1[4];
                ldsm4(bh0, ka0);
                ldsm4(bh1, ka1);
                mma_bf16(s[n0], qa_hi[kb0], bh0[0], bh0[1]);
                mma_bf16(s[n1], qa_hi[kb0], bh1[0], bh1[1]);
                mma_bf16(s[n0], qa_lo[kb0], bh0[0], bh0[1]);
                mma_bf16(s[n1], qa_lo[kb0], bh1[0], bh1[1]);
                mma_bf16(s[n0], qa_hi[kb1], bh0[2], bh0[3]);
                mma_bf16(s[n1], qa_hi[kb1], bh1[2], bh1[3]);
                mma_bf16(s[n0], qa_lo[kb1], bh0[2], bh0[3]);
                mma_bf16(s[n1], qa_lo[kb1], bh1[2], bh1[3]);
                ldsm4(bl0, ka0 + PLANE);
                ldsm4(bl1, ka1 + PLANE);
                mma_bf16(s[n0], qa_hi[kb0], bl0[0], bl0[1]);
                mma_bf16(s[n1], qa_hi[kb0], bl1[0], bl1[1]);
                mma_bf16(s[n0], qa_hi[kb1], bl0[2], bl0[3]);
                mma_bf16(s[n1], qa_hi[kb1], bl1[2], bl1[3]);
            }
        }

        // ---- mask + scale (log2 domain), online softmax ----
        float tm0 = NEG, tm1 = NEG;
        #pragma unroll
        for (int nb = 0; nb < 8; ++nb) {
            int c = (nb << 3) + ((lane & 3) << 1);
            uint32_t mm0 = *(const unsigned short*)(mrd0 + c);
            uint32_t mm1 = *(const unsigned short*)(mrd1 + c);
            s[nb][0] = (mm0 & 0xff) ? NEG : s[nb][0] * K2;
            s[nb][1] = (mm0 >> 8)   ? NEG : s[nb][1] * K2;
            s[nb][2] = (mm1 & 0xff) ? NEG : s[nb][2] * K2;
            s[nb][3] = (mm1 >> 8)   ? NEG : s[nb][3] * K2;
            tm0 = fmaxf(tm0, fmaxf(s[nb][0], s[nb][1]));
            tm1 = fmaxf(tm1, fmaxf(s[nb][2], s[nb][3]));
        }
        tm0 = fmaxf(tm0, __shfl_xor_sync(0xffffffffu, tm0, 1));
        tm0 = fmaxf(tm0, __shfl_xor_sync(0xffffffffu, tm0, 2));
        tm1 = fmaxf(tm1, __shfl_xor_sync(0xffffffffu, tm1, 1));
        tm1 = fmaxf(tm1, __shfl_xor_sync(0xffffffffu, tm1, 2));

        float mn0 = fmaxf(m0r, tm0), mn1 = fmaxf(m1r, tm1);
        float a0 = ex2f(m0r - mn0),  a1 = ex2f(m1r - mn1);
        float k0 = (mn0 > NEG) ? 1.f : 0.f;
        float k1 = (mn1 > NEG) ? 1.f : 0.f;

        float sum0 = 0.f, sum1 = 0.f;
        #pragma unroll
        for (int nb = 0; nb < 8; ++nb) {
            s[nb][0] = ex2f(s[nb][0] - mn0) * k0;
            s[nb][1] = ex2f(s[nb][1] - mn0) * k0;
            s[nb][2] = ex2f(s[nb][2] - mn1) * k1;
            s[nb][3] = ex2f(s[nb][3] - mn1) * k1;
            sum0 += s[nb][0] + s[nb][1];
            sum1 += s[nb][2] + s[nb][3];
        }
        sum0 += __shfl_xor_sync(0xffffffffu, sum0, 1);
        sum0 += __shfl_xor_sync(0xffffffffu, sum0, 2);
        sum1 += __shfl_xor_sync(0xffffffffu, sum1, 1);
        sum1 += __shfl_xor_sync(0xffffffffu, sum1, 2);
        l0r = l0r * a0 + sum0;
        l1r = l1r * a1 + sum1;
        m0r = mn0; m1r = mn1;

        if (__ballot_sync(0xffffffffu, (a0 != 1.f) || (a1 != 1.f))) {
            #pragma unroll
            for (int j = 0; j < 16; ++j) {
                acc[j][0] *= a0; acc[j][1] *= a0; acc[j][2] *= a1; acc[j][3] *= a1;
            }
        }

        // ---- O += P V (bf16x3) ----
        #pragma unroll
        for (int kb = 0; kb < 4; ++kb) {
            uint32_t ah[4], al[4];
            split_pair(s[2*kb][0],   s[2*kb][1],   ah[0], al[0]);
            split_pair(s[2*kb][2],   s[2*kb][3],   ah[1], al[1]);
            split_pair(s[2*kb+1][0], s[2*kb+1][1], ah[2], al[2]);
            split_pair(s[2*kb+1][2], s[2*kb+1][3], ah[3], al[3]);
            uint32_t va = vfb + (uint32_t)(kb * 16 * RSB);
            #pragma unroll
            for (int jp = 0; jp < 8; ++jp) {
                uint32_t bh[4], bl[4];
                ldsm4t(bh, va + jp * 32);
                ldsm4t(bl, va + PLANE + jp * 32);
                mma_bf16(acc[2*jp],   ah, bh[0], bh[1]);
                mma_bf16(acc[2*jp+1], ah, bh[2], bh[3]);
                mma_bf16(acc[2*jp],   ah, bl[0], bl[1]);
                mma_bf16(acc[2*jp+1], ah, bl[2], bl[3]);
                mma_bf16(acc[2*jp],   al, bh[0], bh[1]);
                mma_bf16(acc[2*jp+1], al, bh[2], bh[3]);
            }
        }

        // V buffer free -> issue V(kt+1)
        __syncthreads();
        if (kt + 1 < NIT) fill_V(kt + 1);
        CP_COMMIT();
    }

    // ---- epilogue ----
    float inv0 = (l0r > 0.f) ? (1.0f / l0r) : 0.f;
    float inv1 = (l1r > 0.f) ? (1.0f / l1r) : 0.f;
    const size_t gr0 = (size_t)b * LQ_ + q0 + r0l;
    const size_t gr1 = gr0 + 8;
    #pragma unroll
    for (int j = 0; j < 16; ++j) {
        int c = (j << 3) + ((lane & 3) << 1);
        float2 o0 = make_float2(acc[j][0] * inv0, acc[j][1] * inv0);
        float2 o1 = make_float2(acc[j][2] * inv1, acc[j][3] * inv1);
        *(float2*)(og + gr0 * DH + c) = o0;
        *(float2*)(og + gr1 * DH + c) = o1;
    }
}

} // namespace

extern "C" void kernel_launch(void* const* d_in, const int* in_sizes, int n_in,
                              void* d_out, int out_size) {
    const float* q = (const float*)d_in[0];
    const float* k = (const float*)d_in[1];
    const float* v = (const float*)d_in[2];
    const uint32_t* mask = (const uint32_t*)d_in[3];
    float* out = (float*)d_out;
    (void)in_sizes; (void)n_in; (void)out_size;

    conv_kernel<<<8192, 256>>>(k, v);

    cudaFuncSetAttribute(fa_bf16x3_kernel, cudaFuncAttributeMaxDynamicSharedMemorySize, SM_TOT);
    dim3 grid(LQ_ / BR, B_);
    fa_bf16x3_kernel<<<grid, NTH, SM_TOT>>>(q, mask, out);
}

// round 8
// speedup vs baseline: 1.3585x; 1.3585x over previous
#include <cuda_runtime.h>
#include <cuda_bf16.h>
#include <cuda_fp16.h>
#include <stdint.h>

// Flash attention, B=32, LQ=LK=2048, D=128, fp32 in/out. HMMA path.
// Mask: 4-byte elems (bool promoted); nonzero = masked. score=(q.k)*sqrt(128).
// QK^T: bf16 hi/lo 3-term MMA (validated 5.9e-5).
// PV:   P split to fp16 hi/lo (exact), V single fp16 plane -> 2-term MMA,
//       dropped p*vl ~ 2^-12 => ~3.4e-4 rel err. 17% fewer MMAs, half V traffic.
// R7 = R5 pipeline (QK(kt) issues, softmax+PV(kt-1) overlap the drain).

namespace {

constexpr int B_   = 32;
constexpr int LQ_  = 2048;
constexpr int LK_  = 2048;
constexpr int DH   = 128;
constexpr int BR   = 128;
constexpr int BC   = 64;
constexpr int NTH  = 256;
constexpr int NIT  = LK_ / BC;
constexpr int RSB  = 272;             // 128 bf16 (or 128 fp16) + 16B pad

constexpr int PLANE = BC * RSB;       // 17408 B
constexpr int KSTG  = 2 * PLANE;      // K hi+lo stage: 34816 B
constexpr int SM_K  = 0;              // 2 stages: 69632
constexpr int SM_V  = 2 * KSTG;       // V: 3 stages x 1 fp16 plane
constexpr int SM_MSK = SM_V + 3 * PLANE;   // 121856
constexpr int MROW  = 68;
constexpr int MSKSTG = BR * MROW;     // 8704, x2 stages
constexpr int SM_TOT = SM_MSK + 2 * MSKSTG;   // 139264 B

// Q prologue staging overlays the K region
constexpr int SM_QHI = 0;
constexpr int SM_QLO = BR * RSB;

__device__ __nv_bfloat16 g_khi[(size_t)B_ * LK_ * DH];
__device__ __nv_bfloat16 g_klo[(size_t)B_ * LK_ * DH];
__device__ __half        g_vh [(size_t)B_ * LK_ * DH];

__device__ __forceinline__ uint32_t smem_u32(const void* p) {
    return (uint32_t)__cvta_generic_to_shared(p);
}
__device__ __forceinline__ void cp16(uint32_t dst, const void* src) {
    asm volatile("cp.async.cg.shared.global [%0], [%1], 16;" :: "r"(dst), "l"(src));
}
#define CP_COMMIT() asm volatile("cp.async.commit_group;")
#define CP_WAIT0()  asm volatile("cp.async.wait_group 0;")

__device__ __forceinline__ void ldsm4(uint32_t r[4], uint32_t a) {
    asm volatile("ldmatrix.sync.aligned.m8n8.x4.shared.b16 {%0,%1,%2,%3}, [%4];"
                 : "=r"(r[0]), "=r"(r[1]), "=r"(r[2]), "=r"(r[3]) : "r"(a));
}
__device__ __forceinline__ void ldsm4t(uint32_t r[4], uint32_t a) {
    asm volatile("ldmatrix.sync.aligned.m8n8.x4.trans.shared.b16 {%0,%1,%2,%3}, [%4];"
                 : "=r"(r[0]), "=r"(r[1]), "=r"(r[2]), "=r"(r[3]) : "r"(a));
}
__device__ __forceinline__ void mma_bf16(float d[4], const uint32_t a[4], uint32_t b0, uint32_t b1) {
    asm volatile("mma.sync.aligned.m16n8k16.row.col.f32.bf16.bf16.f32 "
                 "{%0,%1,%2,%3}, {%4,%5,%6,%7}, {%8,%9}, {%0,%1,%2,%3};"
                 : "+f"(d[0]), "+f"(d[1]), "+f"(d[2]), "+f"(d[3])
                 : "r"(a[0]), "r"(a[1]), "r"(a[2]), "r"(a[3]), "r"(b0), "r"(b1));
}
__device__ __forceinline__ void mma_f16(float d[4], const uint32_t a[4], uint32_t b0, uint32_t b1) {
    asm volatile("mma.sync.aligned.m16n8k16.row.col.f32.f16.f16.f32 "
                 "{%0,%1,%2,%3}, {%4,%5,%6,%7}, {%8,%9}, {%0,%1,%2,%3};"
                 : "+f"(d[0]), "+f"(d[1]), "+f"(d[2]), "+f"(d[3])
                 : "r"(a[0]), "r"(a[1]), "r"(a[2]), "r"(a[3]), "r"(b0), "r"(b1));
}
__device__ __forceinline__ float ex2f(float x) {
    float y; asm("ex2.approx.f32 %0, %1;" : "=f"(y) : "f"(x)); return y;
}
__device__ __forceinline__ uint32_t bits2(__nv_bfloat162 h) {
    uint32_t u; __builtin_memcpy(&u, &h, 4); return u;
}
__device__ __forceinline__ uint32_t bits2h(__half2 h) {
    uint32_t u; __builtin_memcpy(&u, &h, 4); return u;
}
__device__ __forceinline__ void split_store(float4 f, char* ph, char* pl) {
    __nv_bfloat16 h0 = __float2bfloat16_rn(f.x);
    __nv_bfloat16 h1 = __float2bfloat16_rn(f.y);
    __nv_bfloat16 h2 = __float2bfloat16_rn(f.z);
    __nv_bfloat16 h3 = __float2bfloat16_rn(f.w);
    *(__nv_bfloat162*)(ph)     = __halves2bfloat162(h0, h1);
    *(__nv_bfloat162*)(ph + 4) = __halves2bfloat162(h2, h3);
    __nv_bfloat16 l0 = __float2bfloat16_rn(f.x - __bfloat162float(h0));
    __nv_bfloat16 l1 = __float2bfloat16_rn(f.y - __bfloat162float(h1));
    __nv_bfloat16 l2 = __float2bfloat16_rn(f.z - __bfloat162float(h2));
    __nv_bfloat16 l3 = __float2bfloat16_rn(f.w - __bfloat162float(h3));
    *(__nv_bfloat162*)(pl)     = __halves2bfloat162(l0, l1);
    *(__nv_bfloat162*)(pl + 4) = __halves2bfloat162(l2, l3);
}
// fp16 hi/lo split of a probability pair (p in [0,1])
__device__ __forceinline__ void split_pair_h(float x, float y, uint32_t& hi, uint32_t& lo) {
    __half hx = __float2half_rn(x);
    __half hy = __float2half_rn(y);
    hi = bits2h(__halves2half2(hx, hy));
    __half lx = __float2half_rn(x - __half2float(hx));
    __half ly = __float2half_rn(y - __half2float(hy));
    lo = bits2h(__halves2half2(lx, ly));
}

__global__ void __launch_bounds__(256, 4)
conv_kernel(const float* __restrict__ kg, const float* __restrict__ vg)
{
    size_t i4 = ((size_t)blockIdx.x * 256 + threadIdx.x) * 4;
    float4 fk = *(const float4*)(kg + i4);
    split_store(fk, (char*)(g_khi + i4), (char*)(g_klo + i4));
    float4 fv = *(const float4*)(vg + i4);
    __half2 v01 = __halves2half2(__float2half_rn(fv.x), __float2half_rn(fv.y));
    __half2 v23 = __halves2half2(__float2half_rn(fv.z), __float2half_rn(fv.w));
    *(__half2*)(g_vh + i4)     = v01;
    *(__half2*)(g_vh + i4 + 2) = v23;
}

__global__ void __launch_bounds__(NTH, 1)
fa_bf16x3_kernel(const float* __restrict__ qg, const uint32_t* __restrict__ mg,
                 float* __restrict__ og)
{
    extern __shared__ char smem[];
    const int tid  = threadIdx.x;
    const int lane = tid & 31;
    const int warp = tid >> 5;
    const int b    = blockIdx.y;
    const int q0   = blockIdx.x * BR;

    const float K2  = 16.3222312f;   // sqrt(128) * log2(e)
    const float NEG = -1e30f;
    const uint32_t sm0 = smem_u32(smem);

    // ---- prologue: Q tile -> bf16 hi/lo smem (overlays K buffers) ----
    {
        const float* qp = qg + ((size_t)b * LQ_ + q0) * DH;
        #pragma unroll
        for (int i = 0; i < 16; ++i) {
            int idx = tid + i * NTH;
            int row = idx >> 5, c4 = idx & 31;
            float4 f = *(const float4*)(qp + (size_t)row * DH + c4 * 4);
            split_store(f, smem + SM_QHI + row * RSB + c4 * 8,
                           smem + SM_QLO + row * RSB + c4 * 8);
        }
    }
    __syncthreads();

    uint32_t qa_hi[8][4], qa_lo[8][4];
    {
        uint32_t base = sm0 + (uint32_t)((warp * 16 + (lane & 15)) * RSB + (lane >> 4) * 16);
        #pragma unroll
        for (int kb = 0; kb < 8; ++kb) {
            ldsm4(qa_hi[kb], base + SM_QHI + kb * 32);
            ldsm4(qa_lo[kb], base + SM_QLO + kb * 32);
        }
    }
    __syncthreads();

    // ---- fill helpers (cp.async) ----
    const size_t kvoff0 = (size_t)b * LK_ * DH + (size_t)(tid & 15) * 8;
    auto fill_K = [&](int kt2) {
        size_t off = kvoff0 + (size_t)kt2 * BC * DH;
        uint32_t dst0 = sm0 + (uint32_t)(SM_K + (kt2 & 1) * KSTG + (tid & 15) * 16);
        #pragma unroll
        for (int i = 0; i < 8; ++i) {
            const int p = i >> 2;
            const int row = (i & 3) * 16 + (tid >> 4);
            const __nv_bfloat16* src = (p == 0 ? g_khi : g_klo) + off + (size_t)row * DH;
            cp16(dst0 + (uint32_t)(p * PLANE + row * RSB), src);
        }
    };
    auto fill_V = [&](int kt2, int vst) {
        size_t off = kvoff0 + (size_t)kt2 * BC * DH;
        uint32_t dst0 = sm0 + (uint32_t)(SM_V + vst * PLANE + (tid & 15) * 16);
        #pragma unroll
        for (int i = 0; i < 4; ++i) {
            const int row = i * 16 + (tid >> 4);
            cp16(dst0 + (uint32_t)(row * RSB), g_vh + off + (size_t)row * DH);
        }
    };

    // ---- mask prefetch (registers) + warp-local smem pack ----
    const int mrow_w = warp * 16 + (lane >> 1);
    const uint32_t* mp_row = mg + (size_t)b * LQ_ * LK_ + (size_t)(q0 + mrow_w) * LK_
                                + (size_t)(lane & 1) * 32;
    uint32_t pk[8];
    auto ldgm = [&](int kt2) {
        const uint32_t* mp = mp_row + (size_t)kt2 * BC;
        #pragma unroll
        for (int j = 0; j < 8; ++j) {
            uint4 m = *(const uint4*)(mp + j * 4);
            pk[j] = (m.x ? 1u : 0u) | ((m.y ? 1u : 0u) << 8) |
                    ((m.z ? 1u : 0u) << 16) | ((m.w ? 1u : 0u) << 24);
        }
    };

    // prologue: K(0), V(0), one group
    fill_K(0);
    fill_V(0, 0);
    CP_COMMIT();
    ldgm(0);

    float acc[16][4];
    #pragma unroll
    for (int j = 0; j < 16; ++j) { acc[j][0]=0.f; acc[j][1]=0.f; acc[j][2]=0.f; acc[j][3]=0.f; }
    float m0r = NEG, m1r = NEG, l0r = 0.f, l1r = 0.f;

    const int r0l = warp * 16 + (lane >> 2);
    const uint32_t kf_lane = (uint32_t)((lane & 7) * RSB + (lane >> 3) * 16);
    const uint32_t vf_lane = (uint32_t)((lane & 15) * RSB + (lane >> 4) * 16);
    char* mskw0 = smem + SM_MSK + mrow_w * MROW + (lane & 1) * 32;
    const char* mrd_base = smem + SM_MSK + r0l * MROW;

    float sA[8][4], sB[8][4];

    // ---- QK^T issue for tile kt into sC (consumed next iteration) ----
    auto qk_issue = [&](int kt, float (&sC)[8][4]) {
        const uint32_t kfb = sm0 + (uint32_t)(SM_K + (kt & 1) * KSTG) + kf_lane;
        #pragma unroll
        for (int nb = 0; nb < 8; ++nb) { sC[nb][0]=0.f; sC[nb][1]=0.f; sC[nb][2]=0.f; sC[nb][3]=0.f; }
        #pragma unroll
        for (int kp2 = 0; kp2 < 4; ++kp2) {
            const int kb0 = 2 * kp2, kb1 = 2 * kp2 + 1;
            #pragma unroll
            for (int nbp = 0; nbp < 4; ++nbp) {
                const int n0 = 2 * nbp, n1 = 2 * nbp + 1;
                const uint32_t ka0 = kfb + (uint32_t)(n0 * 8 * RSB + kp2 * 64);
                const uint32_t ka1 = kfb + (uint32_t)(n1 * 8 * RSB + kp2 * 64);
                uint32_t bh0[4], bh1[4], bl0[4], bl1[4];
                ldsm4(bh0, ka0);
                ldsm4(bh1, ka1);
                mma_bf16(sC[n0], qa_hi[kb0], bh0[0], bh0[1]);
                mma_bf16(sC[n1], qa_hi[kb0], bh1[0], bh1[1]);
                mma_bf16(sC[n0], qa_lo[kb0], bh0[0], bh0[1]);
                mma_bf16(sC[n1], qa_lo[kb0], bh1[0], bh1[1]);
                mma_bf16(sC[n0], qa_hi[kb1], bh0[2], bh0[3]);
                mma_bf16(sC[n1], qa_hi[kb1], bh1[2], bh1[3]);
                mma_bf16(sC[n0], qa_lo[kb1], bh0[2], bh0[3]);
                mma_bf16(sC[n1], qa_lo[kb1], bh1[2], bh1[3]);
                ldsm4(bl0, ka0 + PLANE);
                ldsm4(bl1, ka1 + PLANE);
                mma_bf16(sC[n0], qa_hi[kb0], bl0[0], bl0[1]);
                mma_bf16(sC[n1], qa_hi[kb0], bl1[0], bl1[1]);
                mma_bf16(sC[n0], qa_hi[kb1], bl0[2], bl0[3]);
                mma_bf16(sC[n1], qa_hi[kb1], bl1[2], bl1[3]);
            }
        }
    };

    // ---- softmax + PV (fp16 2-term) for tile ktp ----
    auto softmax_pv = [&](int ktp, float (&s)[8][4]) {
        const char* mrd0 = mrd_base + (ktp & 1) * MSKSTG;
        const char* mrd1 = mrd0 + 8 * MROW;
        float tm0 = NEG, tm1 = NEG;
        #pragma unroll
        for (int nb = 0; nb < 8; ++nb) {
            int c = (nb << 3) + ((lane & 3) << 1);
            uint32_t mm0 = *(const unsigned short*)(mrd0 + c);
            uint32_t mm1 = *(const unsigned short*)(mrd1 + c);
            s[nb][0] = (mm0 & 0xff) ? NEG : s[nb][0] * K2;
            s[nb][1] = (mm0 >> 8)   ? NEG : s[nb][1] * K2;
            s[nb][2] = (mm1 & 0xff) ? NEG : s[nb][2] * K2;
            s[nb][3] = (mm1 >> 8)   ? NEG : s[nb][3] * K2;
            tm0 = fmaxf(tm0, fmaxf(s[nb][0], s[nb][1]));
            tm1 = fmaxf(tm1, fmaxf(s[nb][2], s[nb][3]));
        }
        tm0 = fmaxf(tm0, __shfl_xor_sync(0xffffffffu, tm0, 1));
        tm0 = fmaxf(tm0, __shfl_xor_sync(0xffffffffu, tm0, 2));
        tm1 = fmaxf(tm1, __shfl_xor_sync(0xffffffffu, tm1, 1));
        tm1 = fmaxf(tm1, __shfl_xor_sync(0xffffffffu, tm1, 2));

        float mn0 = fmaxf(m0r, tm0), mn1 = fmaxf(m1r, tm1);
        float a0 = ex2f(m0r - mn0),  a1 = ex2f(m1r - mn1);
        float k0 = (mn0 > NEG) ? 1.f : 0.f;
        float k1 = (mn1 > NEG) ? 1.f : 0.f;

        float sum0 = 0.f, sum1 = 0.f;
        #pragma unroll
        for (int nb = 0; nb < 8; ++nb) {
            s[nb][0] = ex2f(s[nb][0] - mn0) * k0;
            s[nb][1] = ex2f(s[nb][1] - mn0) * k0;
            s[nb][2] = ex2f(s[nb][2] - mn1) * k1;
            s[nb][3] = ex2f(s[nb][3] - mn1) * k1;
            sum0 += s[nb][0] + s[nb][1];
            sum1 += s[nb][2] + s[nb][3];
        }
        sum0 += __shfl_xor_sync(0xffffffffu, sum0, 1);
        sum0 += __shfl_xor_sync(0xffffffffu, sum0, 2);
        sum1 += __shfl_xor_sync(0xffffffffu, sum1, 1);
        sum1 += __shfl_xor_sync(0xffffffffu, sum1, 2);
        l0r = l0r * a0 + sum0;
        l1r = l1r * a1 + sum1;
        m0r = mn0; m1r = mn1;

        if (__ballot_sync(0xffffffffu, (a0 != 1.f) || (a1 != 1.f))) {
            #pragma unroll
            for (int j = 0; j < 16; ++j) {
                acc[j][0] *= a0; acc[j][1] *= a0; acc[j][2] *= a1; acc[j][3] *= a1;
            }
        }

        const int vst = ktp - (ktp / 3) * 3;
        const uint32_t vfb = sm0 + (uint32_t)(SM_V + vst * PLANE) + vf_lane;
        #pragma unroll
        for (int kb = 0; kb < 4; ++kb) {
            uint32_t ph[4], pl[4];
            split_pair_h(s[2*kb][0],   s[2*kb][1],   ph[0], pl[0]);
            split_pair_h(s[2*kb][2],   s[2*kb][3],   ph[1], pl[1]);
            split_pair_h(s[2*kb+1][0], s[2*kb+1][1], ph[2], pl[2]);
            split_pair_h(s[2*kb+1][2], s[2*kb+1][3], ph[3], pl[3]);
            uint32_t va = vfb + (uint32_t)(kb * 16 * RSB);
            #pragma unroll
            for (int jp = 0; jp < 8; ++jp) {
                uint32_t bh[4];
                ldsm4t(bh, va + jp * 32);
                mma_f16(acc[2*jp],   ph, bh[0], bh[1]);
                mma_f16(acc[2*jp+1], ph, bh[2], bh[3]);
                mma_f16(acc[2*jp],   pl, bh[0], bh[1]);
                mma_f16(acc[2*jp+1], pl, bh[2], bh[3]);
            }
        }
    };

    // ---- one pipelined iteration ----
    auto iter = [&](int kt, float (&sC)[8][4], float (&sP)[8][4]) {
        CP_WAIT0();
        __syncthreads();
        if (kt + 1 < NIT) {
            fill_K(kt + 1);
            int vw = kt + 1; vw -= (vw / 3) * 3;
            fill_V(kt + 1, vw);
        }
        CP_COMMIT();

        qk_issue(kt, sC);

        char* mw = mskw0 + (kt & 1) * MSKSTG;
        #pragma unroll
        for (int j = 0; j < 8; ++j) *(uint32_t*)(mw + j * 4) = pk[j];
        __syncwarp();
        if (kt + 1 < NIT) ldgm(kt + 1);

        if (kt > 0) softmax_pv(kt - 1, sP);
    };

    #pragma unroll 1
    for (int kt2 = 0; kt2 < NIT; kt2 += 2) {
        iter(kt2,     sA, sB);
        iter(kt2 + 1, sB, sA);
    }
    softmax_pv(NIT - 1, sB);

    // ---- epilogue ----
    float inv0 = (l0r > 0.f) ? (1.0f / l0r) : 0.f;
    float inv1 = (l1r > 0.f) ? (1.0f / l1r) : 0.f;
    const size_t gr0 = (size_t)b * LQ_ + q0 + r0l;
    const size_t gr1 = gr0 + 8;
    #pragma unroll
    for (int j = 0; j < 16; ++j) {
        int c = (j << 3) + ((lane & 3) << 1);
        float2 o0 = make_float2(acc[j][0] * inv0, acc[j][1] * inv0);
        float2 o1 = make_float2(acc[j][2] * inv1, acc[j][3] * inv1);
        *(float2*)(og + gr0 * DH + c) = o0;
        *(float2*)(og + gr1 * DH + c) = o1;
    }
}

} // namespace

extern "C" void kernel_launch(void* const* d_in, const int* in_sizes, int n_in,
                              void* d_out, int out_size) {
    const float* q = (const float*)d_in[0];
    const float* k = (const float*)d_in[1];
    const float* v = (const float*)d_in[2];
    const uint32_t* mask = (const uint32_t*)d_in[3];
    float* out = (float*)d_out;
    (void)in_sizes; (void)n_in; (void)out_size;

    conv_kernel<<<8192, 256>>>(k, v);

    cudaFuncSetAttribute(fa_bf16x3_kernel, cudaFuncAttributeMaxDynamicSharedMemorySize, SM_TOT);
    dim3 grid(LQ_ / BR, B_);
    fa_bf16x3_kernel<<<grid, NTH, SM_TOT>>>(q, mask, out);
}

// round 9
// speedup vs baseline: 1.4471x; 1.0653x over previous
#include <cuda_runtime.h>
#include <cuda_bf16.h>
#include <cuda_fp16.h>
#include <stdint.h>

// Flash attention, B=32, LQ=LK=2048, D=128, fp32 in/out. HMMA path.
// Mask: 4-byte elems (bool promoted); nonzero = masked. score=(q.k)*sqrt(128).
// R8: QK^T: fp16 hi/lo 3-term MMA (dropped ql*kl ~ 2^-24, error ~0).
//     PV:   single-term fp16(p) * fp16(v) -> 64 MMAs/iter (dropped pl*v ~ 2e-4).
// MMA/iter: 256 (vs R7 320). Wall ~ MMA count on this pipe (validated R7).
// R5 pipeline kept: QK(kt) issues, softmax+PV(kt-1) overlap the drain.

namespace {

constexpr int B_   = 32;
constexpr int LQ_  = 2048;
constexpr int LK_  = 2048;
constexpr int DH   = 128;
constexpr int BR   = 128;
constexpr int BC   = 64;
constexpr int NTH  = 256;
constexpr int NIT  = LK_ / BC;
constexpr int RSB  = 272;             // 128 fp16 + 16B pad

constexpr int PLANE = BC * RSB;       // 17408 B
constexpr int KSTG  = 2 * PLANE;      // K hi+lo stage: 34816 B
constexpr int SM_K  = 0;              // 2 stages: 69632
constexpr int SM_V  = 2 * KSTG;       // V: 3 stages x 1 fp16 plane
constexpr int SM_MSK = SM_V + 3 * PLANE;   // 121856
constexpr int MROW  = 68;
constexpr int MSKSTG = BR * MROW;     // 8704, x2 stages
constexpr int SM_TOT = SM_MSK + 2 * MSKSTG;   // 139264 B

// Q prologue staging overlays the K region
constexpr int SM_QHI = 0;
constexpr int SM_QLO = BR * RSB;

__device__ __half g_khi[(size_t)B_ * LK_ * DH];
__device__ __half g_klo[(size_t)B_ * LK_ * DH];
__device__ __half g_vh [(size_t)B_ * LK_ * DH];

__device__ __forceinline__ uint32_t smem_u32(const void* p) {
    return (uint32_t)__cvta_generic_to_shared(p);
}
__device__ __forceinline__ void cp16(uint32_t dst, const void* src) {
    asm volatile("cp.async.cg.shared.global [%0], [%1], 16;" :: "r"(dst), "l"(src));
}
#define CP_COMMIT() asm volatile("cp.async.commit_group;")
#define CP_WAIT0()  asm volatile("cp.async.wait_group 0;")

__device__ __forceinline__ void ldsm4(uint32_t r[4], uint32_t a) {
    asm volatile("ldmatrix.sync.aligned.m8n8.x4.shared.b16 {%0,%1,%2,%3}, [%4];"
                 : "=r"(r[0]), "=r"(r[1]), "=r"(r[2]), "=r"(r[3]) : "r"(a));
}
__device__ __forceinline__ void ldsm4t(uint32_t r[4], uint32_t a) {
    asm volatile("ldmatrix.sync.aligned.m8n8.x4.trans.shared.b16 {%0,%1,%2,%3}, [%4];"
                 : "=r"(r[0]), "=r"(r[1]), "=r"(r[2]), "=r"(r[3]) : "r"(a));
}
__device__ __forceinline__ void mma_f16(float d[4], const uint32_t a[4], uint32_t b0, uint32_t b1) {
    asm volatile("mma.sync.aligned.m16n8k16.row.col.f32.f16.f16.f32 "
                 "{%0,%1,%2,%3}, {%4,%5,%6,%7}, {%8,%9}, {%0,%1,%2,%3};"
                 : "+f"(d[0]), "+f"(d[1]), "+f"(d[2]), "+f"(d[3])
                 : "r"(a[0]), "r"(a[1]), "r"(a[2]), "r"(a[3]), "r"(b0), "r"(b1));
}
__device__ __forceinline__ float ex2f(float x) {
    float y; asm("ex2.approx.f32 %0, %1;" : "=f"(y) : "f"(x)); return y;
}
__device__ __forceinline__ uint32_t bits2h(__half2 h) {
    uint32_t u; __builtin_memcpy(&u, &h, 4); return u;
}
// fp16 hi/lo split of a float4, stored as 8 bytes hi + 8 bytes lo
__device__ __forceinline__ void split_store_h(float4 f, char* ph, char* pl) {
    __half h0 = __float2half_rn(f.x);
    __half h1 = __float2half_rn(f.y);
    __half h2 = __float2half_rn(f.z);
    __half h3 = __float2half_rn(f.w);
    *(__half2*)(ph)     = __halves2half2(h0, h1);
    *(__half2*)(ph + 4) = __halves2half2(h2, h3);
    __half l0 = __float2half_rn(f.x - __half2float(h0));
    __half l1 = __float2half_rn(f.y - __half2float(h1));
    __half l2 = __float2half_rn(f.z - __half2float(h2));
    __half l3 = __float2half_rn(f.w - __half2float(h3));
    *(__half2*)(pl)     = __halves2half2(l0, l1);
    *(__half2*)(pl + 4) = __halves2half2(l2, l3);
}
__device__ __forceinline__ uint32_t pack_h2(float x, float y) {
    return bits2h(__halves2half2(__float2half_rn(x), __float2half_rn(y)));
}

__global__ void __launch_bounds__(256, 4)
conv_kernel(const float* __restrict__ kg, const float* __restrict__ vg)
{
    size_t i4 = ((size_t)blockIdx.x * 256 + threadIdx.x) * 4;
    float4 fk = *(const float4*)(kg + i4);
    split_store_h(fk, (char*)(g_khi + i4), (char*)(g_klo + i4));
    float4 fv = *(const float4*)(vg + i4);
    *(__half2*)(g_vh + i4)     = __halves2half2(__float2half_rn(fv.x), __float2half_rn(fv.y));
    *(__half2*)(g_vh + i4 + 2) = __halves2half2(__float2half_rn(fv.z), __float2half_rn(fv.w));
}

__global__ void __launch_bounds__(NTH, 1)
fa_fa16_kernel(const float* __restrict__ qg, const uint32_t* __restrict__ mg,
               float* __restrict__ og)
{
    extern __shared__ char smem[];
    const int tid  = threadIdx.x;
    const int lane = tid & 31;
    const int warp = tid >> 5;
    const int b    = blockIdx.y;
    const int q0   = blockIdx.x * BR;

    const float K2  = 16.3222312f;   // sqrt(128) * log2(e)
    const float NEG = -1e30f;
    const uint32_t sm0 = smem_u32(smem);

    // ---- prologue: Q tile -> fp16 hi/lo smem (overlays K buffers) ----
    {
        const float* qp = qg + ((size_t)b * LQ_ + q0) * DH;
        #pragma unroll
        for (int i = 0; i < 16; ++i) {
            int idx = tid + i * NTH;
            int row = idx >> 5, c4 = idx & 31;
            float4 f = *(const float4*)(qp + (size_t)row * DH + c4 * 4);
            split_store_h(f, smem + SM_QHI + row * RSB + c4 * 8,
                             smem + SM_QLO + row * RSB + c4 * 8);
        }
    }
    __syncthreads();

    uint32_t qa_hi[8][4], qa_lo[8][4];
    {
        uint32_t base = sm0 + (uint32_t)((warp * 16 + (lane & 15)) * RSB + (lane >> 4) * 16);
        #pragma unroll
        for (int kb = 0; kb < 8; ++kb) {
            ldsm4(qa_hi[kb], base + SM_QHI + kb * 32);
            ldsm4(qa_lo[kb], base + SM_QLO + kb * 32);
        }
    }
    __syncthreads();

    // ---- fill helpers (cp.async) ----
    const size_t kvoff0 = (size_t)b * LK_ * DH + (size_t)(tid & 15) * 8;
    auto fill_K = [&](int kt2) {
        size_t off = kvoff0 + (size_t)kt2 * BC * DH;
        uint32_t dst0 = sm0 + (uint32_t)(SM_K + (kt2 & 1) * KSTG + (tid & 15) * 16);
        #pragma unroll
        for (int i = 0; i < 8; ++i) {
            const int p = i >> 2;
            const int row = (i & 3) * 16 + (tid >> 4);
            const __half* src = (p == 0 ? g_khi : g_klo) + off + (size_t)row * DH;
            cp16(dst0 + (uint32_t)(p * PLANE + row * RSB), src);
        }
    };
    auto fill_V = [&](int kt2, int vst) {
        size_t off = kvoff0 + (size_t)kt2 * BC * DH;
        uint32_t dst0 = sm0 + (uint32_t)(SM_V + vst * PLANE + (tid & 15) * 16);
        #pragma unroll
        for (int i = 0; i < 4; ++i) {
            const int row = i * 16 + (tid >> 4);
            cp16(dst0 + (uint32_t)(row * RSB), g_vh + off + (size_t)row * DH);
        }
    };

    // ---- mask prefetch (registers) + warp-local smem pack ----
    const int mrow_w = warp * 16 + (lane >> 1);
    const uint32_t* mp_row = mg + (size_t)b * LQ_ * LK_ + (size_t)(q0 + mrow_w) * LK_
                                + (size_t)(lane & 1) * 32;
    uint32_t pk[8];
    auto ldgm = [&](int kt2) {
        const uint32_t* mp = mp_row + (size_t)kt2 * BC;
        #pragma unroll
        for (int j = 0; j < 8; ++j) {
            uint4 m = *(const uint4*)(mp + j * 4);
            pk[j] = (m.x ? 1u : 0u) | ((m.y ? 1u : 0u) << 8) |
                    ((m.z ? 1u : 0u) << 16) | ((m.w ? 1u : 0u) << 24);
        }
    };

    // prologue: K(0), V(0), one group
    fill_K(0);
    fill_V(0, 0);
    CP_COMMIT();
    ldgm(0);

    float acc[16][4];
    #pragma unroll
    for (int j = 0; j < 16; ++j) { acc[j][0]=0.f; acc[j][1]=0.f; acc[j][2]=0.f; acc[j][3]=0.f; }
    float m0r = NEG, m1r = NEG, l0r = 0.f, l1r = 0.f;

    const int r0l = warp * 16 + (lane >> 2);
    const uint32_t kf_lane = (uint32_t)((lane & 7) * RSB + (lane >> 3) * 16);
    const uint32_t vf_lane = (uint32_t)((lane & 15) * RSB + (lane >> 4) * 16);
    char* mskw0 = smem + SM_MSK + mrow_w * MROW + (lane & 1) * 32;
    const char* mrd_base = smem + SM_MSK + r0l * MROW;

    float sA[8][4], sB[8][4];

    // ---- QK^T issue for tile kt into sC (fp16 hi/lo, 3 terms) ----
    auto qk_issue = [&](int kt, float (&sC)[8][4]) {
        const uint32_t kfb = sm0 + (uint32_t)(SM_K + (kt & 1) * KSTG) + kf_lane;
        #pragma unroll
        for (int nb = 0; nb < 8; ++nb) { sC[nb][0]=0.f; sC[nb][1]=0.f; sC[nb][2]=0.f; sC[nb][3]=0.f; }
        #pragma unroll
        for (int kp2 = 0; kp2 < 4; ++kp2) {
            const int kb0 = 2 * kp2, kb1 = 2 * kp2 + 1;
            #pragma unroll
            for (int nbp = 0; nbp < 4; ++nbp) {
                const int n0 = 2 * nbp, n1 = 2 * nbp + 1;
                const uint32_t ka0 = kfb + (uint32_t)(n0 * 8 * RSB + kp2 * 64);
                const uint32_t ka1 = kfb + (uint32_t)(n1 * 8 * RSB + kp2 * 64);
                uint32_t bh0[4], bh1[4], bl0[4], bl1[4];
                ldsm4(bh0, ka0);
                ldsm4(bh1, ka1);
                mma_f16(sC[n0], qa_hi[kb0], bh0[0], bh0[1]);
                mma_f16(sC[n1], qa_hi[kb0], bh1[0], bh1[1]);
                mma_f16(sC[n0], qa_lo[kb0], bh0[0], bh0[1]);
                mma_f16(sC[n1], qa_lo[kb0], bh1[0], bh1[1]);
                mma_f16(sC[n0], qa_hi[kb1], bh0[2], bh0[3]);
                mma_f16(sC[n1], qa_hi[kb1], bh1[2], bh1[3]);
                mma_f16(sC[n0], qa_lo[kb1], bh0[2], bh0[3]);
                mma_f16(sC[n1], qa_lo[kb1], bh1[2], bh1[3]);
                ldsm4(bl0, ka0 + PLANE);
                ldsm4(bl1, ka1 + PLANE);
                mma_f16(sC[n0], qa_hi[kb0], bl0[0], bl0[1]);
                mma_f16(sC[n1], qa_hi[kb0], bl1[0], bl1[1]);
                mma_f16(sC[n0], qa_hi[kb1], bl0[2], bl0[3]);
                mma_f16(sC[n1], qa_hi[kb1], bl1[2], bl1[3]);
            }
        }
    };

    // ---- softmax + PV (single-term fp16) for tile ktp ----
    auto softmax_pv = [&](int ktp, float (&s)[8][4]) {
        const char* mrd0 = mrd_base + (ktp & 1) * MSKSTG;
        const char* mrd1 = mrd0 + 8 * MROW;
        float tm0 = NEG, tm1 = NEG;
        #pragma unroll
        for (int nb = 0; nb < 8; ++nb) {
            int c = (nb << 3) + ((lane & 3) << 1);
            uint32_t mm0 = *(const unsigned short*)(mrd0 + c);
            uint32_t mm1 = *(const unsigned short*)(mrd1 + c);
            s[nb][0] = (mm0 & 0xff) ? NEG : s[nb][0] * K2;
            s[nb][1] = (mm0 >> 8)   ? NEG : s[nb][1] * K2;
            s[nb][2] = (mm1 & 0xff) ? NEG : s[nb][2] * K2;
            s[nb][3] = (mm1 >> 8)   ? NEG : s[nb][3] * K2;
            tm0 = fmaxf(tm0, fmaxf(s[nb][0], s[nb][1]));
            tm1 = fmaxf(tm1, fmaxf(s[nb][2], s[nb][3]));
        }
        tm0 = fmaxf(tm0, __shfl_xor_sync(0xffffffffu, tm0, 1));
        tm0 = fmaxf(tm0, __shfl_xor_sync(0xffffffffu, tm0, 2));
        tm1 = fmaxf(tm1, __shfl_xor_sync(0xffffffffu, tm1, 1));
        tm1 = fmaxf(tm1, __shfl_xor_sync(0xffffffffu, tm1, 2));

        float mn0 = fmaxf(m0r, tm0), mn1 = fmaxf(m1r, tm1);
        float a0 = ex2f(m0r - mn0),  a1 = ex2f(m1r - mn1);
        float k0 = (mn0 > NEG) ? 1.f : 0.f;
        float k1 = (mn1 > NEG) ? 1.f : 0.f;

        float sum0 = 0.f, sum1 = 0.f;
        #pragma unroll
        for (int nb = 0; nb < 8; ++nb) {
            s[nb][0] = ex2f(s[nb][0] - mn0) * k0;
            s[nb][1] = ex2f(s[nb][1] - mn0) * k0;
            s[nb][2] = ex2f(s[nb][2] - mn1) * k1;
            s[nb][3] = ex2f(s[nb][3] - mn1) * k1;
            sum0 += s[nb][0] + s[nb][1];
            sum1 += s[nb][2] + s[nb][3];
        }
        sum0 += __shfl_xor_sync(0xffffffffu, sum0, 1);
        sum0 += __shfl_xor_sync(0xffffffffu, sum0, 2);
        sum1 += __shfl_xor_sync(0xffffffffu, sum1, 1);
        sum1 += __shfl_xor_sync(0xffffffffu, sum1, 2);
        l0r = l0r * a0 + sum0;
        l1r = l1r * a1 + sum1;
        m0r = mn0; m1r = mn1;

        if (__ballot_sync(0xffffffffu, (a0 != 1.f) || (a1 != 1.f))) {
            #pragma unroll
            for (int j = 0; j < 16; ++j) {
                acc[j][0] *= a0; acc[j][1] *= a0; acc[j][2] *= a1; acc[j][3] *= a1;
            }
        }

        const int vst = ktp - (ktp / 3) * 3;
        const uint32_t vfb = sm0 + (uint32_t)(SM_V + vst * PLANE) + vf_lane;
        #pragma unroll
        for (int kb = 0; kb < 4; ++kb) {
            uint32_t ph[4];
            ph[0] = pack_h2(s[2*kb][0],   s[2*kb][1]);
            ph[1] = pack_h2(s[2*kb][2],   s[2*kb][3]);
            ph[2] = pack_h2(s[2*kb+1][0], s[2*kb+1][1]);
            ph[3] = pack_h2(s[2*kb+1][2], s[2*kb+1][3]);
            uint32_t va = vfb + (uint32_t)(kb * 16 * RSB);
            #pragma unroll
            for (int jp = 0; jp < 8; ++jp) {
                uint32_t bh[4];
                ldsm4t(bh, va + jp * 32);
                mma_f16(acc[2*jp],   ph, bh[0], bh[1]);
                mma_f16(acc[2*jp+1], ph, bh[2], bh[3]);
            }
        }
    };

    // ---- one pipelined iteration ----
    auto iter = [&](int kt, float (&sC)[8][4], float (&sP)[8][4]) {
        CP_WAIT0();
        __syncthreads();
        if (kt + 1 < NIT) {
            fill_K(kt + 1);
            int vw = kt + 1; vw -= (vw / 3) * 3;
            fill_V(kt + 1, vw);
        }
        CP_COMMIT();

        qk_issue(kt, sC);

        char* mw = mskw0 + (kt & 1) * MSKSTG;
        #pragma unroll
        for (int j = 0; j < 8; ++j) *(uint32_t*)(mw + j * 4) = pk[j];
        __syncwarp();
        if (kt + 1 < NIT) ldgm(kt + 1);

        if (kt > 0) softmax_pv(kt - 1, sP);
    };

    #pragma unroll 1
    for (int kt2 = 0; kt2 < NIT; kt2 += 2) {
        iter(kt2,     sA, sB);
        iter(kt2 + 1, sB, sA);
    }
    softmax_pv(NIT - 1, sB);

    // ---- epilogue ----
    float inv0 = (l0r > 0.f) ? (1.0f / l0r) : 0.f;
    float inv1 = (l1r > 0.f) ? (1.0f / l1r) : 0.f;
    const size_t gr0 = (size_t)b * LQ_ + q0 + r0l;
    const size_t gr1 = gr0 + 8;
    #pragma unroll
    for (int j = 0; j < 16; ++j) {
        int c = (j << 3) + ((lane & 3) << 1);
        float2 o0 = make_float2(acc[j][0] * inv0, acc[j][1] * inv0);
        float2 o1 = make_float2(acc[j][2] * inv1, acc[j][3] * inv1);
        *(float2*)(og + gr0 * DH + c) = o0;
        *(float2*)(og + gr1 * DH + c) = o1;
    }
}

} // namespace

extern "C" void kernel_launch(void* const* d_in, const int* in_sizes, int n_in,
                              void* d_out, int out_size) {
    const float* q = (const float*)d_in[0];
    const float* k = (const float*)d_in[1];
    const float* v = (const float*)d_in[2];
    const uint32_t* mask = (const uint32_t*)d_in[3];
    float* out = (float*)d_out;
    (void)in_sizes; (void)n_in; (void)out_size;

    conv_kernel<<<8192, 256>>>(k, v);

    cudaFuncSetAttribute(fa_fa16_kernel, cudaFuncAttributeMaxDynamicSharedMemorySize, SM_TOT);
    dim3 grid(LQ_ / BR, B_);
    fa_fa16_kernel<<<grid, NTH, SM_TOT>>>(q, mask, out);
}